// round 3
// baseline (speedup 1.0000x reference)
#include <cuda_runtime.h>
#include <math.h>

#define Hn   1024
#define En   1024
#define Tn   4096
#define Vn   50257
#define INPn 2049

// ---- scratch (no allocations allowed) ----
__device__ float g_att[En];        // column sums of hiddens
__device__ float g_h[Hn];          // LSTM output h
__device__ float g_exp[Vn];        // exp(logits)
__device__ float g_sum;            // sum of exps

struct GateParams {
    const float* Wi[4];
    const float* Wh[4];
    const float* bi[4];
    const float* bh[4];
};

// Zero the atomic accumulators (tiny).
__global__ void k_init() {
    g_att[threadIdx.x] = 0.f;
    if (threadIdx.x == 0) g_sum = 0.f;
}

// Column sum of hiddens [T, E] (the softmax over the size-1 axis is all ones,
// and the sigmoid scores are dead code). float4: rows are 4KB each -> aligned.
__global__ void k_colsum(const float* __restrict__ hid) {
    const float4* h4 = (const float4*)hid;       // [Tn][256] float4
    int t0 = blockIdx.x * 16;                    // 256 blocks x 16 rows
    float4 a = make_float4(0.f, 0.f, 0.f, 0.f);
    #pragma unroll
    for (int t = 0; t < 16; t++) {
        float4 v = __ldg(&h4[(size_t)(t0 + t) * 256 + threadIdx.x]);
        a.x += v.x; a.y += v.y; a.z += v.z; a.w += v.w;
    }
    int e = threadIdx.x * 4;
    atomicAdd(&g_att[e + 0], a.x);
    atomicAdd(&g_att[e + 1], a.y);
    atomicAdd(&g_att[e + 2], a.z);
    atomicAdd(&g_att[e + 3], a.w);
}

// One block per output row r: compute all 4 gate pre-activations, then the
// LSTM cell update, writing g_h[r] directly. 8 warps: 2 per gate.
__global__ void k_gates(GateParams gp,
                        const float* __restrict__ sen,
                        const float* __restrict__ curh,
                        const float* __restrict__ curc,
                        const int*   __restrict__ pos) {
    __shared__ float sx[INPn];
    __shared__ float shh[Hn];
    __shared__ float sp[8];
    int r    = blockIdx.x;
    int tid  = threadIdx.x;
    int wid  = tid >> 5;
    int lane = tid & 31;
    int gate = wid >> 1;
    int half = wid & 1;

    // pos_index dtype-defensive read
    int ib = __ldg(pos);
    float posv = ((unsigned)ib < (1u << 20)) ? (float)ib : __int_as_float(ib);

    // stage x = [sen | att | pos] and cur_h into smem
    for (int i = tid; i < INPn; i += 256)
        sx[i] = (i < En) ? __ldg(&sen[i]) : (i < En + Hn) ? g_att[i - En] : posv;
    for (int i = tid; i < Hn; i += 256)
        shh[i] = __ldg(&curh[i]);
    __syncthreads();

    const float*  Wi  = gp.Wi[gate] + (size_t)r * INPn;
    const float4* Wh4 = (const float4*)(gp.Wh[gate] + (size_t)r * Hn); // 4KB rows -> aligned

    float acc = 0.f;
    #pragma unroll 8
    for (int c = half * 32 + lane; c < INPn; c += 64)
        acc += __ldg(&Wi[c]) * sx[c];
    #pragma unroll 4
    for (int c4 = half * 32 + lane; c4 < Hn / 4; c4 += 64) {
        float4 w = __ldg(&Wh4[c4]);
        int c = c4 * 4;
        acc += w.x * shh[c] + w.y * shh[c + 1] + w.z * shh[c + 2] + w.w * shh[c + 3];
    }

    #pragma unroll
    for (int o = 16; o; o >>= 1)
        acc += __shfl_down_sync(0xffffffffu, acc, o);
    if (lane == 0) sp[wid] = acc;
    __syncthreads();

    if (tid == 0) {
        float yi = sp[0] + sp[1] + __ldg(&gp.bi[0][r]) + __ldg(&gp.bh[0][r]);
        float yf = sp[2] + sp[3] + __ldg(&gp.bi[1][r]) + __ldg(&gp.bh[1][r]);
        float yg = sp[4] + sp[5] + __ldg(&gp.bi[2][r]) + __ldg(&gp.bh[2][r]);
        float yo = sp[6] + sp[7] + __ldg(&gp.bi[3][r]) + __ldg(&gp.bh[3][r]);
        float i = 1.f / (1.f + expf(-yi));
        float f = 1.f / (1.f + expf(-yf));
        float g = tanhf(yg);
        float o = 1.f / (1.f + expf(-yo));
        float c = f * __ldg(&curc[r]) + i * g;
        g_h[r] = o * tanhf(c);
    }
}

// logits + exp + partial softmax-sum. Block = 128 v-columns; 8 warps each own
// a 128-row h-slice; h staged in smem; smem cross-warp reduction; exp written
// to g_exp; block partial sum of exps atomicAdd'ed into g_sum.
__global__ void k_logits(const float* __restrict__ dout) {
    __shared__ float sh[Hn];
    __shared__ float red[8 * 128];
    int tid  = threadIdx.x;
    int wid  = tid >> 5;
    int lane = tid & 31;
    int v0   = blockIdx.x * 128;

    for (int i = tid; i < Hn; i += 256) sh[i] = g_h[i];
    __syncthreads();

    float a0 = 0.f, a1 = 0.f, a2 = 0.f, a3 = 0.f;
    bool ok0 = v0 + lane +  0 < Vn;
    bool ok1 = v0 + lane + 32 < Vn;
    bool ok2 = v0 + lane + 64 < Vn;
    bool ok3 = v0 + lane + 96 < Vn;
    const float* base = dout + (size_t)(wid * 128) * Vn + v0 + lane;
    #pragma unroll 4
    for (int h = 0; h < 128; h++) {
        float hv = sh[wid * 128 + h];
        const float* row = base + (size_t)h * Vn;
        if (ok0) a0 += hv * __ldg(row +  0);
        if (ok1) a1 += hv * __ldg(row + 32);
        if (ok2) a2 += hv * __ldg(row + 64);
        if (ok3) a3 += hv * __ldg(row + 96);
    }
    red[wid * 128 + lane +  0] = a0;
    red[wid * 128 + lane + 32] = a1;
    red[wid * 128 + lane + 64] = a2;
    red[wid * 128 + lane + 96] = a3;
    __syncthreads();

    float e = 0.f;
    if (tid < 128) {
        int v = v0 + tid;
        if (v < Vn) {
            float l = 0.f;
            #pragma unroll
            for (int w = 0; w < 8; w++) l += red[w * 128 + tid];
            e = expf(l);               // |logit| small; max-subtraction unnecessary
            g_exp[v] = e;
        }
    }
    // sum of exps across the (up to) 128 active threads: 4 warp reductions
    if (tid < 128) {
        #pragma unroll
        for (int o = 16; o; o >>= 1)
            e += __shfl_down_sync(0xffffffffu, e, o);
        if (lane == 0) atomicAdd(&g_sum, e);
    }
}

__global__ void k_norm(float* __restrict__ out) {
    int v = blockIdx.x * blockDim.x + threadIdx.x;
    float inv = 1.f / g_sum;
    if (v < Vn) out[v] = g_exp[v] * inv;
}

extern "C" void kernel_launch(void* const* d_in, const int* in_sizes, int n_in,
                              void* d_out, int out_size) {
    const float* sen  = (const float*)d_in[0];
    const float* hid  = (const float*)d_in[1];
    const float* dout = (const float*)d_in[2];
    GateParams gp;
    for (int g = 0; g < 4; g++) {
        gp.Wi[g] = (const float*)d_in[3 + 4 * g];
        gp.Wh[g] = (const float*)d_in[4 + 4 * g];
        gp.bi[g] = (const float*)d_in[5 + 4 * g];
        gp.bh[g] = (const float*)d_in[6 + 4 * g];
    }
    const float* curh = (const float*)d_in[19];
    const float* curc = (const float*)d_in[20];
    const int*   pos  = (const int*)d_in[21];
    float* out = (float*)d_out;

    k_init<<<1, En>>>();
    k_colsum<<<Tn / 16, 256>>>(hid);
    k_gates<<<Hn, 256>>>(gp, sen, curh, curc, pos);
    k_logits<<<(Vn + 127) / 128, 256>>>(dout);
    k_norm<<<(Vn + 255) / 256, 256>>>(out);
}

// round 4
// speedup vs baseline: 1.2098x; 1.2098x over previous
#include <cuda_runtime.h>
#include <math.h>

#define Hn   1024
#define En   1024
#define Tn   4096
#define Vn   50257
#define INPn 2049

// ---- scratch (no allocations allowed) ----
__device__ float g_att[En];        // column sums of hiddens
__device__ float g_h[Hn];          // LSTM output h
__device__ float g_exp[Vn];        // exp(logits)
__device__ float g_sum;            // sum of exps

struct GateParams {
    const float* Wi[4];
    const float* Wh[4];
    const float* bi[4];
    const float* bh[4];
};

// Zero the atomic accumulators (tiny).
__global__ void k_init() {
    g_att[threadIdx.x] = 0.f;
    if (threadIdx.x == 0) g_sum = 0.f;
}

// Column sum of hiddens [T, E] (softmax over size-1 axis == all ones; the
// sigmoid scores are dead code). float4: rows are 4KB each -> aligned.
__global__ void k_colsum(const float* __restrict__ hid) {
    const float4* h4 = (const float4*)hid;       // [Tn][256] float4
    int t0 = blockIdx.x * 16;                    // 256 blocks x 16 rows
    float4 a = make_float4(0.f, 0.f, 0.f, 0.f);
    #pragma unroll
    for (int t = 0; t < 16; t++) {
        float4 v = __ldg(&h4[(size_t)(t0 + t) * 256 + threadIdx.x]);
        a.x += v.x; a.y += v.y; a.z += v.z; a.w += v.w;
    }
    int e = threadIdx.x * 4;
    atomicAdd(&g_att[e + 0], a.x);
    atomicAdd(&g_att[e + 1], a.y);
    atomicAdd(&g_att[e + 2], a.z);
    atomicAdd(&g_att[e + 3], a.w);
}

// One block per output row r: all 4 gate pre-activations + LSTM cell update,
// writing g_h[r] directly. 8 warps: 2 per gate.
__global__ void k_gates(GateParams gp,
                        const float* __restrict__ sen,
                        const float* __restrict__ curh,
                        const float* __restrict__ curc,
                        const int*   __restrict__ pos) {
    __shared__ float sx[INPn];
    __shared__ float shh[Hn];
    __shared__ float sp[8];
    int r    = blockIdx.x;
    int tid  = threadIdx.x;
    int wid  = tid >> 5;
    int lane = tid & 31;
    int gate = wid >> 1;
    int half = wid & 1;

    // pos_index dtype-defensive read
    int ib = __ldg(pos);
    float posv = ((unsigned)ib < (1u << 20)) ? (float)ib : __int_as_float(ib);

    for (int i = tid; i < INPn; i += 256)
        sx[i] = (i < En) ? __ldg(&sen[i]) : (i < En + Hn) ? g_att[i - En] : posv;
    for (int i = tid; i < Hn; i += 256)
        shh[i] = __ldg(&curh[i]);
    __syncthreads();

    const float*  Wi  = gp.Wi[gate] + (size_t)r * INPn;
    const float4* Wh4 = (const float4*)(gp.Wh[gate] + (size_t)r * Hn); // 4KB rows

    float acc = 0.f;
    #pragma unroll 8
    for (int c = half * 32 + lane; c < INPn; c += 64)
        acc += __ldg(&Wi[c]) * sx[c];
    #pragma unroll 4
    for (int c4 = half * 32 + lane; c4 < Hn / 4; c4 += 64) {
        float4 w = __ldg(&Wh4[c4]);
        int c = c4 * 4;
        acc += w.x * shh[c] + w.y * shh[c + 1] + w.z * shh[c + 2] + w.w * shh[c + 3];
    }

    #pragma unroll
    for (int o = 16; o; o >>= 1)
        acc += __shfl_down_sync(0xffffffffu, acc, o);
    if (lane == 0) sp[wid] = acc;
    __syncthreads();

    if (tid == 0) {
        float yi = sp[0] + sp[1] + __ldg(&gp.bi[0][r]) + __ldg(&gp.bh[0][r]);
        float yf = sp[2] + sp[3] + __ldg(&gp.bi[1][r]) + __ldg(&gp.bh[1][r]);
        float yg = sp[4] + sp[5] + __ldg(&gp.bi[2][r]) + __ldg(&gp.bh[2][r]);
        float yo = sp[6] + sp[7] + __ldg(&gp.bi[3][r]) + __ldg(&gp.bh[3][r]);
        float i = 1.f / (1.f + expf(-yi));
        float f = 1.f / (1.f + expf(-yf));
        float g = tanhf(yg);
        float o = 1.f / (1.f + expf(-yo));
        float c = f * __ldg(&curc[r]) + i * g;
        g_h[r] = o * tanhf(c);
    }
}

// logits + exp + partial softmax-sum. Block = 128 v-columns; 8 warps each own
// a 128-row h-slice. Fast path (392/393 blocks): no predicates, explicit
// 32-load register batch per 8-h step to maximize loads in flight.
__global__ void k_logits(const float* __restrict__ dout) {
    __shared__ float sh[Hn];
    __shared__ float red[8 * 128];
    int tid  = threadIdx.x;
    int wid  = tid >> 5;
    int lane = tid & 31;
    int v0   = blockIdx.x * 128;

    for (int i = tid; i < Hn; i += 256) sh[i] = g_h[i];
    __syncthreads();

    float a0 = 0.f, a1 = 0.f, a2 = 0.f, a3 = 0.f;
    const float* base = dout + (size_t)(wid * 128) * Vn + v0 + lane;

    if (v0 + 128 <= Vn) {
        // full tile: unpredicated, batch 8 h-rows x 4 columns = 32 loads
        #pragma unroll 1
        for (int hh = 0; hh < 128; hh += 8) {
            float r[8][4];
            #pragma unroll
            for (int u = 0; u < 8; u++) {
                const float* row = base + (size_t)(hh + u) * Vn;
                r[u][0] = __ldg(row +  0);
                r[u][1] = __ldg(row + 32);
                r[u][2] = __ldg(row + 64);
                r[u][3] = __ldg(row + 96);
            }
            #pragma unroll
            for (int u = 0; u < 8; u++) {
                float hv = sh[wid * 128 + hh + u];
                a0 += hv * r[u][0];
                a1 += hv * r[u][1];
                a2 += hv * r[u][2];
                a3 += hv * r[u][3];
            }
        }
    } else {
        // tail block: guarded
        bool ok0 = v0 + lane +  0 < Vn;
        bool ok1 = v0 + lane + 32 < Vn;
        bool ok2 = v0 + lane + 64 < Vn;
        bool ok3 = v0 + lane + 96 < Vn;
        for (int h = 0; h < 128; h++) {
            float hv = sh[wid * 128 + h];
            const float* row = base + (size_t)h * Vn;
            if (ok0) a0 += hv * __ldg(row +  0);
            if (ok1) a1 += hv * __ldg(row + 32);
            if (ok2) a2 += hv * __ldg(row + 64);
            if (ok3) a3 += hv * __ldg(row + 96);
        }
    }
    red[wid * 128 + lane +  0] = a0;
    red[wid * 128 + lane + 32] = a1;
    red[wid * 128 + lane + 64] = a2;
    red[wid * 128 + lane + 96] = a3;
    __syncthreads();

    float e = 0.f;
    if (tid < 128) {
        int v = v0 + tid;
        if (v < Vn) {
            float l = 0.f;
            #pragma unroll
            for (int w = 0; w < 8; w++) l += red[w * 128 + tid];
            e = expf(l);               // |logit| small; max-subtraction unnecessary
            g_exp[v] = e;
        }
        #pragma unroll
        for (int o = 16; o; o >>= 1)
            e += __shfl_down_sync(0xffffffffu, e, o);
        if (lane == 0) atomicAdd(&g_sum, e);
    }
}

__global__ void k_norm(float* __restrict__ out) {
    int v = blockIdx.x * blockDim.x + threadIdx.x;
    float inv = 1.f / g_sum;
    if (v < Vn) out[v] = g_exp[v] * inv;
}

extern "C" void kernel_launch(void* const* d_in, const int* in_sizes, int n_in,
                              void* d_out, int out_size) {
    const float* sen  = (const float*)d_in[0];
    const float* hid  = (const float*)d_in[1];
    const float* dout = (const float*)d_in[2];
    GateParams gp;
    for (int g = 0; g < 4; g++) {
        gp.Wi[g] = (const float*)d_in[3 + 4 * g];
        gp.Wh[g] = (const float*)d_in[4 + 4 * g];
        gp.bi[g] = (const float*)d_in[5 + 4 * g];
        gp.bh[g] = (const float*)d_in[6 + 4 * g];
    }
    const float* curh = (const float*)d_in[19];
    const float* curc = (const float*)d_in[20];
    const int*   pos  = (const int*)d_in[21];
    float* out = (float*)d_out;

    k_init<<<1, En>>>();
    k_colsum<<<Tn / 16, 256>>>(hid);
    k_gates<<<Hn, 256>>>(gp, sen, curh, curc, pos);
    k_logits<<<(Vn + 127) / 128, 256>>>(dout);
    k_norm<<<(Vn + 255) / 256, 256>>>(out);
}

// round 5
// speedup vs baseline: 2.1295x; 1.7602x over previous
#include <cuda_runtime.h>
#include <math.h>

#define Hn   1024
#define En   1024
#define Tn   4096
#define Vn   50257
#define INPn 2049

// ---- scratch (no allocations allowed) ----
__device__ float g_att[En];          // column sums of hiddens
__device__ float g_h[Hn];            // LSTM output h
__device__ float g_part[4 * Vn];     // per-h-slice partial logits
__device__ float g_exp[Vn];          // exp(logits)
__device__ float g_sum;              // sum of exps

struct GateParams {
    const float* Wi[4];
    const float* Wh[4];
    const float* bi[4];
    const float* bh[4];
};

// Zero the atomic accumulators (tiny).
__global__ void k_init() {
    g_att[threadIdx.x] = 0.f;
    if (threadIdx.x == 0) g_sum = 0.f;
}

// Column sum of hiddens [T, E] (softmax over size-1 axis == all ones; the
// sigmoid scores are dead code). float4: rows are 4KB each -> aligned.
__global__ void k_colsum(const float* __restrict__ hid) {
    const float4* h4 = (const float4*)hid;       // [Tn][256] float4
    int t0 = blockIdx.x * 16;                    // 256 blocks x 16 rows
    float4 a = make_float4(0.f, 0.f, 0.f, 0.f);
    #pragma unroll
    for (int t = 0; t < 16; t++) {
        float4 v = __ldg(&h4[(size_t)(t0 + t) * 256 + threadIdx.x]);
        a.x += v.x; a.y += v.y; a.z += v.z; a.w += v.w;
    }
    int e = threadIdx.x * 4;
    atomicAdd(&g_att[e + 0], a.x);
    atomicAdd(&g_att[e + 1], a.y);
    atomicAdd(&g_att[e + 2], a.z);
    atomicAdd(&g_att[e + 3], a.w);
}

// One block per output row r: all 4 gate pre-activations + LSTM cell update,
// writing g_h[r] directly. 8 warps: 2 per gate.
__global__ void k_gates(GateParams gp,
                        const float* __restrict__ sen,
                        const float* __restrict__ curh,
                        const float* __restrict__ curc,
                        const int*   __restrict__ pos) {
    __shared__ float sx[INPn];
    __shared__ float shh[Hn];
    __shared__ float sp[8];
    int r    = blockIdx.x;
    int tid  = threadIdx.x;
    int wid  = tid >> 5;
    int lane = tid & 31;
    int gate = wid >> 1;
    int half = wid & 1;

    // pos_index dtype-defensive read
    int ib = __ldg(pos);
    float posv = ((unsigned)ib < (1u << 20)) ? (float)ib : __int_as_float(ib);

    for (int i = tid; i < INPn; i += 256)
        sx[i] = (i < En) ? __ldg(&sen[i]) : (i < En + Hn) ? g_att[i - En] : posv;
    for (int i = tid; i < Hn; i += 256)
        shh[i] = __ldg(&curh[i]);
    __syncthreads();

    const float*  Wi  = gp.Wi[gate] + (size_t)r * INPn;
    const float4* Wh4 = (const float4*)(gp.Wh[gate] + (size_t)r * Hn); // 4KB rows

    float acc = 0.f;
    #pragma unroll 8
    for (int c = half * 32 + lane; c < INPn; c += 64)
        acc += __ldg(&Wi[c]) * sx[c];
    #pragma unroll 4
    for (int c4 = half * 32 + lane; c4 < Hn / 4; c4 += 64) {
        float4 w = __ldg(&Wh4[c4]);
        int c = c4 * 4;
        acc += w.x * shh[c] + w.y * shh[c + 1] + w.z * shh[c + 2] + w.w * shh[c + 3];
    }

    #pragma unroll
    for (int o = 16; o; o >>= 1)
        acc += __shfl_down_sync(0xffffffffu, acc, o);
    if (lane == 0) sp[wid] = acc;
    __syncthreads();

    if (tid == 0) {
        float yi = sp[0] + sp[1] + __ldg(&gp.bi[0][r]) + __ldg(&gp.bh[0][r]);
        float yf = sp[2] + sp[3] + __ldg(&gp.bi[1][r]) + __ldg(&gp.bh[1][r]);
        float yg = sp[4] + sp[5] + __ldg(&gp.bi[2][r]) + __ldg(&gp.bh[2][r]);
        float yo = sp[6] + sp[7] + __ldg(&gp.bi[3][r]) + __ldg(&gp.bh[3][r]);
        float i = 1.f / (1.f + expf(-yi));
        float f = 1.f / (1.f + expf(-yf));
        float g = tanhf(yg);
        float o = 1.f / (1.f + expf(-yo));
        float c = f * __ldg(&curc[r]) + i * g;
        g_h[r] = o * tanhf(c);
    }
}

// Partial logits. Grid (393, 4): blockIdx.x = 128-v tile, blockIdx.y = 256-row
// h-window. 8 warps/block, each owns 32 h-rows. ~8 blocks/SM -> 64 warps/SM,
// so DRAM latency is covered by warp count, not per-warp batching alone.
__global__ void __launch_bounds__(256) k_logits(const float* __restrict__ dout) {
    __shared__ float sh[256];
    __shared__ float red[8 * 128];
    int tid  = threadIdx.x;
    int wid  = tid >> 5;
    int lane = tid & 31;
    int v0   = blockIdx.x * 128;
    int hblk = blockIdx.y * 256;

    sh[tid] = g_h[hblk + tid];
    __syncthreads();

    float a0 = 0.f, a1 = 0.f, a2 = 0.f, a3 = 0.f;
    const float* base = dout + (size_t)(hblk + wid * 32) * Vn + v0 + lane;

    if (v0 + 128 <= Vn) {
        #pragma unroll 1
        for (int hh = 0; hh < 32; hh += 8) {
            float r[8][4];
            #pragma unroll
            for (int u = 0; u < 8; u++) {
                const float* row = base + (size_t)(hh + u) * Vn;
                r[u][0] = __ldg(row +  0);
                r[u][1] = __ldg(row + 32);
                r[u][2] = __ldg(row + 64);
                r[u][3] = __ldg(row + 96);
            }
            #pragma unroll
            for (int u = 0; u < 8; u++) {
                float hv = sh[wid * 32 + hh + u];
                a0 += hv * r[u][0];
                a1 += hv * r[u][1];
                a2 += hv * r[u][2];
                a3 += hv * r[u][3];
            }
        }
    } else {
        bool ok0 = v0 + lane +  0 < Vn;
        bool ok1 = v0 + lane + 32 < Vn;
        bool ok2 = v0 + lane + 64 < Vn;
        bool ok3 = v0 + lane + 96 < Vn;
        for (int h = 0; h < 32; h++) {
            float hv = sh[wid * 32 + h];
            const float* row = base + (size_t)h * Vn;
            if (ok0) a0 += hv * __ldg(row +  0);
            if (ok1) a1 += hv * __ldg(row + 32);
            if (ok2) a2 += hv * __ldg(row + 64);
            if (ok3) a3 += hv * __ldg(row + 96);
        }
    }
    red[wid * 128 + lane +  0] = a0;
    red[wid * 128 + lane + 32] = a1;
    red[wid * 128 + lane + 64] = a2;
    red[wid * 128 + lane + 96] = a3;
    __syncthreads();

    if (tid < 128) {
        int v = v0 + tid;
        if (v < Vn) {
            float l = 0.f;
            #pragma unroll
            for (int w = 0; w < 8; w++) l += red[w * 128 + tid];
            g_part[blockIdx.y * Vn + v] = l;   // plain store: deterministic
        }
    }
}

// Sum the 4 h-slice partials, exponentiate, accumulate softmax denominator.
__global__ void k_expsum() {
    __shared__ float red[32];
    int tid = threadIdx.x;
    int v   = blockIdx.x * 1024 + tid;
    float e = 0.f;
    if (v < Vn) {
        float l = g_part[v] + g_part[Vn + v] + g_part[2 * Vn + v] + g_part[3 * Vn + v];
        e = expf(l);                 // |logit| small; max-subtraction unnecessary
        g_exp[v] = e;
    }
    #pragma unroll
    for (int o = 16; o; o >>= 1)
        e += __shfl_down_sync(0xffffffffu, e, o);
    if ((tid & 31) == 0) red[tid >> 5] = e;
    __syncthreads();
    if (tid < 32) {
        float s = red[tid];
        #pragma unroll
        for (int o = 16; o; o >>= 1)
            s += __shfl_down_sync(0xffffffffu, s, o);
        if (tid == 0) atomicAdd(&g_sum, s);
    }
}

__global__ void k_norm(float* __restrict__ out) {
    int v = blockIdx.x * blockDim.x + threadIdx.x;
    float inv = 1.f / g_sum;
    if (v < Vn) out[v] = g_exp[v] * inv;
}

extern "C" void kernel_launch(void* const* d_in, const int* in_sizes, int n_in,
                              void* d_out, int out_size) {
    const float* sen  = (const float*)d_in[0];
    const float* hid  = (const float*)d_in[1];
    const float* dout = (const float*)d_in[2];
    GateParams gp;
    for (int g = 0; g < 4; g++) {
        gp.Wi[g] = (const float*)d_in[3 + 4 * g];
        gp.Wh[g] = (const float*)d_in[4 + 4 * g];
        gp.bi[g] = (const float*)d_in[5 + 4 * g];
        gp.bh[g] = (const float*)d_in[6 + 4 * g];
    }
    const float* curh = (const float*)d_in[19];
    const float* curc = (const float*)d_in[20];
    const int*   pos  = (const int*)d_in[21];
    float* out = (float*)d_out;

    k_init<<<1, En>>>();
    k_colsum<<<Tn / 16, 256>>>(hid);
    k_gates<<<Hn, 256>>>(gp, sen, curh, curc, pos);
    k_logits<<<dim3((Vn + 127) / 128, 4), 256>>>(dout);
    k_expsum<<<(Vn + 1023) / 1024, 1024>>>();
    k_norm<<<(Vn + 255) / 256, 256>>>(out);
}

// round 6
// speedup vs baseline: 2.1346x; 1.0024x over previous
#include <cuda_runtime.h>
#include <math.h>

#define Hn   1024
#define En   1024
#define Tn   4096
#define Vn   50257
#define INPn 2049

// ---- scratch (no allocations allowed) ----
__device__ float g_att[En];          // column sums of hiddens
__device__ float g_h[Hn];            // LSTM output h
__device__ float g_part[4 * Vn];     // per-h-slice partial logits
__device__ float g_exp[Vn];          // exp(logits)
__device__ float g_sum;              // sum of exps

struct GateParams {
    const float* Wi[4];
    const float* Wh[4];
    const float* bi[4];
    const float* bh[4];
};

// Zero the atomic accumulators (tiny).
__global__ void k_init() {
    g_att[threadIdx.x] = 0.f;
    if (threadIdx.x == 0) g_sum = 0.f;
}

// Column sum of hiddens [T, E] (softmax over size-1 axis == all ones; the
// sigmoid scores are dead code). float4: rows are 4KB each -> aligned.
__global__ void k_colsum(const float* __restrict__ hid) {
    const float4* h4 = (const float4*)hid;       // [Tn][256] float4
    int t0 = blockIdx.x * 16;                    // 256 blocks x 16 rows
    float4 a = make_float4(0.f, 0.f, 0.f, 0.f);
    #pragma unroll
    for (int t = 0; t < 16; t++) {
        float4 v = __ldg(&h4[(size_t)(t0 + t) * 256 + threadIdx.x]);
        a.x += v.x; a.y += v.y; a.z += v.z; a.w += v.w;
    }
    int e = threadIdx.x * 4;
    atomicAdd(&g_att[e + 0], a.x);
    atomicAdd(&g_att[e + 1], a.y);
    atomicAdd(&g_att[e + 2], a.z);
    atomicAdd(&g_att[e + 3], a.w);
}

// One block per output row r: all 4 gate pre-activations + LSTM cell update,
// writing g_h[r] directly. 8 warps: 2 per gate.
__global__ void k_gates(GateParams gp,
                        const float* __restrict__ sen,
                        const float* __restrict__ curh,
                        const float* __restrict__ curc,
                        const int*   __restrict__ pos) {
    __shared__ float sx[INPn];
    __shared__ float shh[Hn];
    __shared__ float sp[8];
    int r    = blockIdx.x;
    int tid  = threadIdx.x;
    int wid  = tid >> 5;
    int lane = tid & 31;
    int gate = wid >> 1;
    int half = wid & 1;

    // pos_index dtype-defensive read
    int ib = __ldg(pos);
    float posv = ((unsigned)ib < (1u << 20)) ? (float)ib : __int_as_float(ib);

    for (int i = tid; i < INPn; i += 256)
        sx[i] = (i < En) ? __ldg(&sen[i]) : (i < En + Hn) ? g_att[i - En] : posv;
    for (int i = tid; i < Hn; i += 256)
        shh[i] = __ldg(&curh[i]);
    __syncthreads();

    const float*  Wi  = gp.Wi[gate] + (size_t)r * INPn;
    const float4* Wh4 = (const float4*)(gp.Wh[gate] + (size_t)r * Hn); // 4KB rows

    float acc = 0.f;
    #pragma unroll 8
    for (int c = half * 32 + lane; c < INPn; c += 64)
        acc += __ldg(&Wi[c]) * sx[c];
    #pragma unroll 4
    for (int c4 = half * 32 + lane; c4 < Hn / 4; c4 += 64) {
        float4 w = __ldg(&Wh4[c4]);
        int c = c4 * 4;
        acc += w.x * shh[c] + w.y * shh[c + 1] + w.z * shh[c + 2] + w.w * shh[c + 3];
    }

    #pragma unroll
    for (int o = 16; o; o >>= 1)
        acc += __shfl_down_sync(0xffffffffu, acc, o);
    if (lane == 0) sp[wid] = acc;
    __syncthreads();

    if (tid == 0) {
        float yi = sp[0] + sp[1] + __ldg(&gp.bi[0][r]) + __ldg(&gp.bh[0][r]);
        float yf = sp[2] + sp[3] + __ldg(&gp.bi[1][r]) + __ldg(&gp.bh[1][r]);
        float yg = sp[4] + sp[5] + __ldg(&gp.bi[2][r]) + __ldg(&gp.bh[2][r]);
        float yo = sp[6] + sp[7] + __ldg(&gp.bi[3][r]) + __ldg(&gp.bh[3][r]);
        float i = 1.f / (1.f + expf(-yi));
        float f = 1.f / (1.f + expf(-yf));
        float g = tanhf(yg);
        float o = 1.f / (1.f + expf(-yo));
        float c = f * __ldg(&curc[r]) + i * g;
        g_h[r] = o * tanhf(c);
    }
}

// Partial logits. Grid (393, 4): blockIdx.x = 128-v tile, blockIdx.y = 256-row
// h-window. 8 warps/block, each owns 32 h-rows. ~8 blocks/SM -> 64 warps/SM,
// so DRAM latency is covered by warp count, not per-warp batching alone.
__global__ void __launch_bounds__(256) k_logits(const float* __restrict__ dout) {
    __shared__ float sh[256];
    __shared__ float red[8 * 128];
    int tid  = threadIdx.x;
    int wid  = tid >> 5;
    int lane = tid & 31;
    int v0   = blockIdx.x * 128;
    int hblk = blockIdx.y * 256;

    sh[tid] = g_h[hblk + tid];
    __syncthreads();

    float a0 = 0.f, a1 = 0.f, a2 = 0.f, a3 = 0.f;
    const float* base = dout + (size_t)(hblk + wid * 32) * Vn + v0 + lane;

    if (v0 + 128 <= Vn) {
        #pragma unroll 1
        for (int hh = 0; hh < 32; hh += 8) {
            float r[8][4];
            #pragma unroll
            for (int u = 0; u < 8; u++) {
                const float* row = base + (size_t)(hh + u) * Vn;
                r[u][0] = __ldg(row +  0);
                r[u][1] = __ldg(row + 32);
                r[u][2] = __ldg(row + 64);
                r[u][3] = __ldg(row + 96);
            }
            #pragma unroll
            for (int u = 0; u < 8; u++) {
                float hv = sh[wid * 32 + hh + u];
                a0 += hv * r[u][0];
                a1 += hv * r[u][1];
                a2 += hv * r[u][2];
                a3 += hv * r[u][3];
            }
        }
    } else {
        bool ok0 = v0 + lane +  0 < Vn;
        bool ok1 = v0 + lane + 32 < Vn;
        bool ok2 = v0 + lane + 64 < Vn;
        bool ok3 = v0 + lane + 96 < Vn;
        for (int h = 0; h < 32; h++) {
            float hv = sh[wid * 32 + h];
            const float* row = base + (size_t)h * Vn;
            if (ok0) a0 += hv * __ldg(row +  0);
            if (ok1) a1 += hv * __ldg(row + 32);
            if (ok2) a2 += hv * __ldg(row + 64);
            if (ok3) a3 += hv * __ldg(row + 96);
        }
    }
    red[wid * 128 + lane +  0] = a0;
    red[wid * 128 + lane + 32] = a1;
    red[wid * 128 + lane + 64] = a2;
    red[wid * 128 + lane + 96] = a3;
    __syncthreads();

    if (tid < 128) {
        int v = v0 + tid;
        if (v < Vn) {
            float l = 0.f;
            #pragma unroll
            for (int w = 0; w < 8; w++) l += red[w * 128 + tid];
            g_part[blockIdx.y * Vn + v] = l;   // plain store: deterministic
        }
    }
}

// Sum the 4 h-slice partials, exponentiate, accumulate softmax denominator.
__global__ void k_expsum() {
    __shared__ float red[32];
    int tid = threadIdx.x;
    int v   = blockIdx.x * 1024 + tid;
    float e = 0.f;
    if (v < Vn) {
        float l = g_part[v] + g_part[Vn + v] + g_part[2 * Vn + v] + g_part[3 * Vn + v];
        e = expf(l);                 // |logit| small; max-subtraction unnecessary
        g_exp[v] = e;
    }
    #pragma unroll
    for (int o = 16; o; o >>= 1)
        e += __shfl_down_sync(0xffffffffu, e, o);
    if ((tid & 31) == 0) red[tid >> 5] = e;
    __syncthreads();
    if (tid < 32) {
        float s = red[tid];
        #pragma unroll
        for (int o = 16; o; o >>= 1)
            s += __shfl_down_sync(0xffffffffu, s, o);
        if (tid == 0) atomicAdd(&g_sum, s);
    }
}

__global__ void k_norm(float* __restrict__ out) {
    int v = blockIdx.x * blockDim.x + threadIdx.x;
    float inv = 1.f / g_sum;
    if (v < Vn) out[v] = g_exp[v] * inv;
}

extern "C" void kernel_launch(void* const* d_in, const int* in_sizes, int n_in,
                              void* d_out, int out_size) {
    const float* sen  = (const float*)d_in[0];
    const float* hid  = (const float*)d_in[1];
    const float* dout = (const float*)d_in[2];
    GateParams gp;
    for (int g = 0; g < 4; g++) {
        gp.Wi[g] = (const float*)d_in[3 + 4 * g];
        gp.Wh[g] = (const float*)d_in[4 + 4 * g];
        gp.bi[g] = (const float*)d_in[5 + 4 * g];
        gp.bh[g] = (const float*)d_in[6 + 4 * g];
    }
    const float* curh = (const float*)d_in[19];
    const float* curc = (const float*)d_in[20];
    const int*   pos  = (const int*)d_in[21];
    float* out = (float*)d_out;

    k_init<<<1, En>>>();
    k_colsum<<<Tn / 16, 256>>>(hid);
    k_gates<<<Hn, 256>>>(gp, sen, curh, curc, pos);
    k_logits<<<dim3((Vn + 127) / 128, 4), 256>>>(dout);
    k_expsum<<<(Vn + 1023) / 1024, 1024>>>();
    k_norm<<<(Vn + 255) / 256, 256>>>(out);
}

// round 7
// speedup vs baseline: 2.1805x; 1.0215x over previous
#include <cuda_runtime.h>
#include <math.h>

#define Hn   1024
#define En   1024
#define Tn   4096
#define Vn   50257
#define INPn 2049
#define NVT  393          // number of 128-wide v tiles

// ---- scratch (no allocations allowed) ----
__device__ float g_att[En];          // column sums of hiddens
__device__ float g_h[Hn];            // LSTM output h
__device__ float g_part[4 * Vn];     // per-h-slice partial logits
__device__ float g_exp[Vn];          // exp(logits)
__device__ float g_sum;              // sum of exps
__device__ int   g_cnt[NVT];         // per-v-tile arrival counters

struct GateParams {
    const float* Wi[4];
    const float* Wh[4];
    const float* bi[4];
    const float* bh[4];
};

// Zero accumulators + tile counters (re-runs every graph replay).
__global__ void k_init() {
    int t = threadIdx.x;
    g_att[t] = 0.f;
    if (t < NVT) g_cnt[t] = 0;
    if (t == 0) g_sum = 0.f;
}

// Column sum of hiddens [T, E] (softmax over size-1 axis == all ones; the
// sigmoid scores are dead code). float4: rows are 4KB each -> aligned.
__global__ void k_colsum(const float* __restrict__ hid) {
    const float4* h4 = (const float4*)hid;       // [Tn][256] float4
    int t0 = blockIdx.x * 16;                    // 256 blocks x 16 rows
    float4 a = make_float4(0.f, 0.f, 0.f, 0.f);
    #pragma unroll
    for (int t = 0; t < 16; t++) {
        float4 v = __ldg(&h4[(size_t)(t0 + t) * 256 + threadIdx.x]);
        a.x += v.x; a.y += v.y; a.z += v.z; a.w += v.w;
    }
    int e = threadIdx.x * 4;
    atomicAdd(&g_att[e + 0], a.x);
    atomicAdd(&g_att[e + 1], a.y);
    atomicAdd(&g_att[e + 2], a.z);
    atomicAdd(&g_att[e + 3], a.w);
}

// One block per output row r: all 4 gate pre-activations + LSTM cell update,
// writing g_h[r] directly. 8 warps: 2 per gate.
__global__ void k_gates(GateParams gp,
                        const float* __restrict__ sen,
                        const float* __restrict__ curh,
                        const float* __restrict__ curc,
                        const int*   __restrict__ pos) {
    __shared__ float sx[INPn];
    __shared__ float shh[Hn];
    __shared__ float sp[8];
    int r    = blockIdx.x;
    int tid  = threadIdx.x;
    int wid  = tid >> 5;
    int lane = tid & 31;
    int gate = wid >> 1;
    int half = wid & 1;

    // pos_index dtype-defensive read
    int ib = __ldg(pos);
    float posv = ((unsigned)ib < (1u << 20)) ? (float)ib : __int_as_float(ib);

    for (int i = tid; i < INPn; i += 256)
        sx[i] = (i < En) ? __ldg(&sen[i]) : (i < En + Hn) ? g_att[i - En] : posv;
    for (int i = tid; i < Hn; i += 256)
        shh[i] = __ldg(&curh[i]);
    __syncthreads();

    const float*  Wi  = gp.Wi[gate] + (size_t)r * INPn;
    const float4* Wh4 = (const float4*)(gp.Wh[gate] + (size_t)r * Hn); // 4KB rows

    float acc = 0.f;
    #pragma unroll 8
    for (int c = half * 32 + lane; c < INPn; c += 64)
        acc += __ldcs(&Wi[c]) * sx[c];
    #pragma unroll 4
    for (int c4 = half * 32 + lane; c4 < Hn / 4; c4 += 64) {
        float4 w = __ldcs(&Wh4[c4]);
        int c = c4 * 4;
        acc += w.x * shh[c] + w.y * shh[c + 1] + w.z * shh[c + 2] + w.w * shh[c + 3];
    }

    #pragma unroll
    for (int o = 16; o; o >>= 1)
        acc += __shfl_down_sync(0xffffffffu, acc, o);
    if (lane == 0) sp[wid] = acc;
    __syncthreads();

    if (tid == 0) {
        float yi = sp[0] + sp[1] + __ldg(&gp.bi[0][r]) + __ldg(&gp.bh[0][r]);
        float yf = sp[2] + sp[3] + __ldg(&gp.bi[1][r]) + __ldg(&gp.bh[1][r]);
        float yg = sp[4] + sp[5] + __ldg(&gp.bi[2][r]) + __ldg(&gp.bh[2][r]);
        float yo = sp[6] + sp[7] + __ldg(&gp.bi[3][r]) + __ldg(&gp.bh[3][r]);
        float i = 1.f / (1.f + expf(-yi));
        float f = 1.f / (1.f + expf(-yf));
        float g = tanhf(yg);
        float o = 1.f / (1.f + expf(-yo));
        float c = f * __ldg(&curc[r]) + i * g;
        g_h[r] = o * tanhf(c);
    }
}

// Partial logits + fused exp/softmax-sum on last tile arrival.
// Grid (393, 4): blockIdx.x = 128-v tile, blockIdx.y = 256-row h-window.
// launch_bounds(256,4): 4 blocks/SM -> 64-reg budget so the 32-load batch is
// genuinely register-resident (MLP ~8 lines/warp x 32 warps/SM >> latency BDP).
__global__ void __launch_bounds__(256, 4) k_logits(const float* __restrict__ dout) {
    __shared__ float sh[256];
    __shared__ float red[8 * 128];
    __shared__ int   slast;
    int tid  = threadIdx.x;
    int wid  = tid >> 5;
    int lane = tid & 31;
    int v0   = blockIdx.x * 128;
    int hblk = blockIdx.y * 256;

    sh[tid] = g_h[hblk + tid];
    __syncthreads();

    float a0 = 0.f, a1 = 0.f, a2 = 0.f, a3 = 0.f;
    const float* base = dout + (size_t)(hblk + wid * 32) * Vn + v0 + lane;

    if (v0 + 128 <= Vn) {
        #pragma unroll 1
        for (int hh = 0; hh < 32; hh += 8) {
            float r[8][4];
            #pragma unroll
            for (int u = 0; u < 8; u++) {
                const float* row = base + (size_t)(hh + u) * Vn;
                r[u][0] = __ldcs(row +  0);
                r[u][1] = __ldcs(row + 32);
                r[u][2] = __ldcs(row + 64);
                r[u][3] = __ldcs(row + 96);
            }
            #pragma unroll
            for (int u = 0; u < 8; u++) {
                float hv = sh[wid * 32 + hh + u];
                a0 += hv * r[u][0];
                a1 += hv * r[u][1];
                a2 += hv * r[u][2];
                a3 += hv * r[u][3];
            }
        }
    } else {
        bool ok0 = v0 + lane +  0 < Vn;
        bool ok1 = v0 + lane + 32 < Vn;
        bool ok2 = v0 + lane + 64 < Vn;
        bool ok3 = v0 + lane + 96 < Vn;
        for (int h = 0; h < 32; h++) {
            float hv = sh[wid * 32 + h];
            const float* row = base + (size_t)h * Vn;
            if (ok0) a0 += hv * __ldcs(row +  0);
            if (ok1) a1 += hv * __ldcs(row + 32);
            if (ok2) a2 += hv * __ldcs(row + 64);
            if (ok3) a3 += hv * __ldcs(row + 96);
        }
    }
    red[wid * 128 + lane +  0] = a0;
    red[wid * 128 + lane + 32] = a1;
    red[wid * 128 + lane + 64] = a2;
    red[wid * 128 + lane + 96] = a3;
    __syncthreads();

    if (tid < 128) {
        int v = v0 + tid;
        if (v < Vn) {
            float l = 0.f;
            #pragma unroll
            for (int w = 0; w < 8; w++) l += red[w * 128 + tid];
            g_part[blockIdx.y * Vn + v] = l;   // plain store
        }
    }
    __syncthreads();

    // last-arrival fusion: the 4th block for this v-tile finishes the softmax
    // numerator (deterministic fixed-order sum of the 4 partials).
    if (tid == 0) {
        __threadfence();
        slast = (atomicAdd(&g_cnt[blockIdx.x], 1) == 3);
    }
    __syncthreads();
    if (slast) {
        float e = 0.f;
        if (tid < 128) {
            int v = v0 + tid;
            if (v < Vn) {
                float l = g_part[v] + g_part[Vn + v]
                        + g_part[2 * Vn + v] + g_part[3 * Vn + v];
                e = expf(l);           // |logit| small; max-subtraction unnecessary
                g_exp[v] = e;
            }
            #pragma unroll
            for (int o = 16; o; o >>= 1)
                e += __shfl_down_sync(0xffffffffu, e, o);
            if (lane == 0) atomicAdd(&g_sum, e);
        }
    }
}

__global__ void k_norm(float* __restrict__ out) {
    int v = blockIdx.x * blockDim.x + threadIdx.x;
    float inv = 1.f / g_sum;
    if (v < Vn) out[v] = g_exp[v] * inv;
}

extern "C" void kernel_launch(void* const* d_in, const int* in_sizes, int n_in,
                              void* d_out, int out_size) {
    const float* sen  = (const float*)d_in[0];
    const float* hid  = (const float*)d_in[1];
    const float* dout = (const float*)d_in[2];
    GateParams gp;
    for (int g = 0; g < 4; g++) {
        gp.Wi[g] = (const float*)d_in[3 + 4 * g];
        gp.Wh[g] = (const float*)d_in[4 + 4 * g];
        gp.bi[g] = (const float*)d_in[5 + 4 * g];
        gp.bh[g] = (const float*)d_in[6 + 4 * g];
    }
    const float* curh = (const float*)d_in[19];
    const float* curc = (const float*)d_in[20];
    const int*   pos  = (const int*)d_in[21];
    float* out = (float*)d_out;

    k_init<<<1, En>>>();
    k_colsum<<<Tn / 16, 256>>>(hid);
    k_gates<<<Hn, 256>>>(gp, sen, curh, curc, pos);
    k_logits<<<dim3(NVT, 4), 256>>>(dout);
    k_norm<<<(Vn + 255) / 256, 256>>>(out);
}